// round 1
// baseline (speedup 1.0000x reference)
#include <cuda_runtime.h>
#include <math.h>

#define NDST 25000
#define DIM 128
#define DT_DIM 100
#define DQ 228          // 128 + 100
#define DK 356          // 128 + 128 + 100
#define UW 712          // 2 heads * 356
#define EMAX 400000
#define LEAKYC 0.2f
#define EPSC 1e-5f

// ---------------- device scratch (no allocations allowed) ----------------
__device__ float d_cq[DIM];                    // bq + Wq_time @ cos(b_t)
__device__ float d_QB[NDST * 2];               // Q_h . bk_h per dst per head
__device__ int   d_counts[NDST];
__device__ int   d_starts[NDST];
__device__ int   d_cursor[NDST];
__device__ int   d_incl[NDST];
__device__ int   d_csum[64];
__device__ int   d_coff[64];
__device__ int   d_order[EMAX];
__device__ float d_U[(size_t)NDST * UW];       // 71 MB
__device__ float d_T[(size_t)NDST * UW];       // 71 MB
__device__ float d_AGG[(size_t)NDST * DIM];    // 12.8 MB

// ---------------- tiny setup kernels ----------------
__global__ void k_zero() {
    int i = blockIdx.x * blockDim.x + threadIdx.x;
    if (i < NDST) { d_counts[i] = 0; d_cursor[i] = 0; }
}

__global__ void k_prep(const float* __restrict__ Wq, const float* __restrict__ bq,
                       const float* __restrict__ b_t) {
    int j = threadIdx.x;           // 128 threads
    float s = bq[j];
    for (int t = 0; t < DT_DIM; t++)
        s = fmaf(Wq[j * DQ + DIM + t], cosf(b_t[t]), s);
    d_cq[j] = s;
}

// ---------------- counting sort of edges by dst ----------------
__global__ void k_hist(const int* __restrict__ dst, int E) {
    int e = blockIdx.x * blockDim.x + threadIdx.x;
    if (e < E) atomicAdd(&d_counts[dst[e]], 1);
}

__global__ void k_scan1() {
    __shared__ int sm[512];
    int b = blockIdx.x, t = threadIdx.x;
    int i = b * 512 + t;
    sm[t] = (i < NDST) ? d_counts[i] : 0;
    __syncthreads();
    for (int off = 1; off < 512; off <<= 1) {
        int x = (t >= off) ? sm[t - off] : 0;
        __syncthreads();
        sm[t] += x;
        __syncthreads();
    }
    if (i < NDST) d_incl[i] = sm[t];
    if (t == 511) d_csum[b] = sm[t];
}

__global__ void k_scan2(int nch) {
    if (threadIdx.x == 0) {
        int run = 0;
        for (int b = 0; b < nch; b++) { d_coff[b] = run; run += d_csum[b]; }
    }
}

__global__ void k_scan3() {
    int i = blockIdx.x * blockDim.x + threadIdx.x;
    if (i < NDST) d_starts[i] = d_incl[i] - d_counts[i] + d_coff[i >> 9];
}

__global__ void k_scatter(const int* __restrict__ dst, int E) {
    int e = blockIdx.x * blockDim.x + threadIdx.x;
    if (e < E) {
        int d = dst[e];
        int pos = d_starts[d] + atomicAdd(&d_cursor[d], 1);
        d_order[pos] = e;
    }
}

// ---------------- Q projection + score-folding matrix U ----------------
// qn[n,j]  = sum_i h[n,i] * Wq[j,i] + cq[j]
// U[n,h,c] = sum_{jj<64} qn[n,h*64+jj] * Wk[(h*64+jj)*356 + c]
// QB[n,h]  = sum_{jj<64} qn[n,h*64+jj] * bk[h*64+jj]
__global__ void k_qu(const float* __restrict__ h, const float* __restrict__ Wq,
                     const float* __restrict__ Wk, const float* __restrict__ bk) {
    __shared__ float hs[32][128];
    __shared__ float qns[32][128];
    int nb = blockIdx.x * 32;
    int tid = threadIdx.x;

    for (int idx = tid; idx < 32 * 128; idx += 256) {
        int n = idx >> 7, i = idx & 127;
        hs[n][i] = (nb + n < NDST) ? h[(size_t)(nb + n) * DIM + i] : 0.f;
    }
    __syncthreads();

    int j = tid & 127, n0 = tid >> 7;
    float acc[16];
#pragma unroll
    for (int k = 0; k < 16; k++) acc[k] = 0.f;
    for (int i = 0; i < 128; i++) {
        float wq = Wq[j * DQ + i];
#pragma unroll
        for (int k = 0; k < 16; k++) acc[k] = fmaf(hs[n0 + 2 * k][i], wq, acc[k]);
    }
    float c0 = d_cq[j];
#pragma unroll
    for (int k = 0; k < 16; k++) qns[n0 + 2 * k][j] = acc[k] + c0;
    __syncthreads();

    // per-dst score bias from bk
    for (int idx = tid; idx < 64; idx += 256) {
        int n = idx >> 1, hh = idx & 1;
        float s = 0.f;
        for (int jj = 0; jj < 64; jj++)
            s = fmaf(qns[n][hh * 64 + jj], bk[hh * 64 + jj], s);
        if (nb + n < NDST) d_QB[(nb + n) * 2 + hh] = s;
    }

    // U
    for (int idx = tid; idx < 32 * UW; idx += 256) {
        int n = idx / UW, r = idx % UW;
        int hh = r / DK, c = r % DK;
        float s = 0.f;
        const float* wkp = Wk + (size_t)(hh * 64) * DK + c;
#pragma unroll 8
        for (int jj = 0; jj < 64; jj++)
            s = fmaf(qns[n][hh * 64 + jj], wkp[(size_t)jj * DK], s);
        if (nb + n < NDST) d_U[(size_t)(nb + n) * UW + r] = s;
    }
}

// ---------------- warp-per-dst fused attention (online softmax) ----------------
__global__ void k_attn(const float* __restrict__ h, const float* __restrict__ f,
                       const float* __restrict__ dt, const int* __restrict__ src_idx,
                       const float* __restrict__ w_t, const float* __restrict__ b_t) {
    int wid = (blockIdx.x * blockDim.x + threadIdx.x) >> 5;
    int l = threadIdx.x & 31;
    if (wid >= NDST) return;
    int n = wid;
    int start = d_starts[n];
    int cnt = d_counts[n];

    float Ua[12], Ub[12], Ta[12], Tb[12];
    const float* up = d_U + (size_t)n * UW;
#pragma unroll
    for (int k = 0; k < 12; k++) {
        int c = 32 * k + l;
        bool v = c < DK;
        Ua[k] = v ? up[c] : 0.f;
        Ub[k] = v ? up[DK + c] : 0.f;
        Ta[k] = 0.f; Tb[k] = 0.f;
    }
    float qb0 = d_QB[n * 2], qb1 = d_QB[n * 2 + 1];
    float tw0 = w_t[l],        tb0 = b_t[l];
    float tw1 = w_t[l + 32],   tb1 = b_t[l + 32];
    float tw2 = w_t[l + 64],   tb2 = b_t[l + 64];
    float tw3 = 0.f, tb3 = 0.f;
    if (l < 4) { tw3 = w_t[l + 96]; tb3 = b_t[l + 96]; }

    float ninf = __int_as_float(0xff800000);
    float m0 = ninf, m1 = ninf, s0 = 0.f, s1 = 0.f;

    for (int i = 0; i < cnt; i++) {
        int e = d_order[start + i];
        int src = src_idx[e];
        float dtv = dt[e];
        const float* hp = h + (size_t)src * DIM;
        const float* fp = f + (size_t)e * DIM;
        float kv[12];
#pragma unroll
        for (int k = 0; k < 4; k++) kv[k] = hp[32 * k + l];
#pragma unroll
        for (int k = 0; k < 4; k++) kv[4 + k] = fp[32 * k + l];
        kv[8]  = cosf(__fadd_rn(__fmul_rn(dtv, tw0), tb0));
        kv[9]  = cosf(__fadd_rn(__fmul_rn(dtv, tw1), tb1));
        kv[10] = cosf(__fadd_rn(__fmul_rn(dtv, tw2), tb2));
        kv[11] = (l < 4) ? cosf(__fadd_rn(__fmul_rn(dtv, tw3), tb3)) : 0.f;

        float sc0 = 0.f, sc1 = 0.f;
#pragma unroll
        for (int k = 0; k < 12; k++) {
            sc0 = fmaf(Ua[k], kv[k], sc0);
            sc1 = fmaf(Ub[k], kv[k], sc1);
        }
#pragma unroll
        for (int o = 16; o > 0; o >>= 1) {
            sc0 += __shfl_xor_sync(0xffffffffu, sc0, o);
            sc1 += __shfl_xor_sync(0xffffffffu, sc1, o);
        }
        sc0 += qb0; sc1 += qb1;
        sc0 = sc0 >= 0.f ? sc0 : LEAKYC * sc0;   // leaky relu
        sc1 = sc1 >= 0.f ? sc1 : LEAKYC * sc1;

        float nm0 = fmaxf(m0, sc0), nm1 = fmaxf(m1, sc1);
        float cr0 = __expf(m0 - nm0), cr1 = __expf(m1 - nm1);
        float e0 = __expf(sc0 - nm0), e1 = __expf(sc1 - nm1);
        s0 = s0 * cr0 + e0;
        s1 = s1 * cr1 + e1;
#pragma unroll
        for (int k = 0; k < 12; k++) {
            Ta[k] = fmaf(Ta[k], cr0, e0 * kv[k]);
            Tb[k] = fmaf(Tb[k], cr1, e1 * kv[k]);
        }
        m0 = nm0; m1 = nm1;
    }

    float r0 = s0 > 0.f ? 1.f / s0 : 0.f;
    float r1 = s1 > 0.f ? 1.f / s1 : 0.f;
    float* tp = d_T + (size_t)n * UW;
#pragma unroll
    for (int k = 0; k < 12; k++) {
        int c = 32 * k + l;
        if (c < DK) {
            tp[c]      = Ta[k] * r0;
            tp[DK + c] = Tb[k] * r1;
        }
    }
}

// ---------------- agg = T @ Wv^T (+ bv when node has edges) ----------------
__global__ void k_agg(const float* __restrict__ Wv, const float* __restrict__ bv) {
    __shared__ float Ts[16 * UW];   // 45.5 KB
    int nb = blockIdx.x * 16;
    int tid = threadIdx.x;
    for (int idx = tid; idx < 16 * UW; idx += 256) {
        int n = idx / UW;
        Ts[idx] = (nb + n < NDST) ? d_T[(size_t)(nb + n) * UW + idx % UW] : 0.f;
    }
    __syncthreads();

    int o = tid & 127, n0 = tid >> 7;
    int head = o >> 6;
    int coff = head * DK;
    float acc[8];
#pragma unroll
    for (int k = 0; k < 8; k++) acc[k] = 0.f;
    const float* wvp = Wv + (size_t)o * DK;
    for (int c = 0; c < DK; c++) {
        float wv = wvp[c];
#pragma unroll
        for (int k = 0; k < 8; k++)
            acc[k] = fmaf(Ts[(n0 + 2 * k) * UW + coff + c], wv, acc[k]);
    }
#pragma unroll
    for (int k = 0; k < 8; k++) {
        int n = nb + n0 + 2 * k;
        if (n < NDST) {
            float b = (d_counts[n] > 0) ? bv[o] : 0.f;
            d_AGG[(size_t)n * DIM + o] = acc[k] + b;
        }
    }
}

// ---------------- rst = relu([agg, h] @ Wout^T + bout) -> LayerNorm ----------------
__global__ void k_out(const float* __restrict__ h, const float* __restrict__ Wout,
                      const float* __restrict__ bout, const float* __restrict__ ln_w,
                      const float* __restrict__ ln_b, float* __restrict__ out) {
    __shared__ float As[16][128];
    __shared__ float Hs[16][128];
    __shared__ float Rs[16][128];
    int nb = blockIdx.x * 16;
    int tid = threadIdx.x;
    for (int idx = tid; idx < 16 * 128; idx += 256) {
        int n = idx >> 7, i = idx & 127;
        bool v = nb + n < NDST;
        As[n][i] = v ? d_AGG[(size_t)(nb + n) * DIM + i] : 0.f;
        Hs[n][i] = v ? h[(size_t)(nb + n) * DIM + i] : 0.f;
    }
    __syncthreads();

    int o = tid & 127, n0 = tid >> 7;
    float bo = bout[o];
    float acc[8];
#pragma unroll
    for (int k = 0; k < 8; k++) acc[k] = bo;
    const float* wp = Wout + (size_t)o * 256;
    for (int p = 0; p < 128; p++) {
        float w1 = wp[p], w2 = wp[128 + p];
#pragma unroll
        for (int k = 0; k < 8; k++) {
            acc[k] = fmaf(As[n0 + 2 * k][p], w1, acc[k]);
            acc[k] = fmaf(Hs[n0 + 2 * k][p], w2, acc[k]);
        }
    }
#pragma unroll
    for (int k = 0; k < 8; k++) Rs[n0 + 2 * k][o] = fmaxf(acc[k], 0.f);
    __syncthreads();

    // LayerNorm: 8 warps, 2 rows each
    int w = tid >> 5, l = tid & 31;
    for (int rr = 0; rr < 2; rr++) {
        int n = w * 2 + rr;
        float v0 = Rs[n][l], v1 = Rs[n][l + 32], v2 = Rs[n][l + 64], v3 = Rs[n][l + 96];
        float s = v0 + v1 + v2 + v3;
#pragma unroll
        for (int off = 16; off > 0; off >>= 1) s += __shfl_xor_sync(0xffffffffu, s, off);
        float mu = s * (1.f / 128.f);
        float dd0 = v0 - mu, dd1 = v1 - mu, dd2 = v2 - mu, dd3 = v3 - mu;
        float vs = dd0 * dd0 + dd1 * dd1 + dd2 * dd2 + dd3 * dd3;
#pragma unroll
        for (int off = 16; off > 0; off >>= 1) vs += __shfl_xor_sync(0xffffffffu, vs, off);
        float rstd = rsqrtf(vs * (1.f / 128.f) + EPSC);
        int ng = nb + n;
        if (ng < NDST) {
            out[(size_t)ng * DIM + l]      = dd0 * rstd * ln_w[l]      + ln_b[l];
            out[(size_t)ng * DIM + l + 32] = dd1 * rstd * ln_w[l + 32] + ln_b[l + 32];
            out[(size_t)ng * DIM + l + 64] = dd2 * rstd * ln_w[l + 64] + ln_b[l + 64];
            out[(size_t)ng * DIM + l + 96] = dd3 * rstd * ln_w[l + 96] + ln_b[l + 96];
        }
    }
}

// ---------------- launch ----------------
extern "C" void kernel_launch(void* const* d_in, const int* in_sizes, int n_in,
                              void* d_out, int out_size) {
    const float* h       = (const float*)d_in[0];
    const float* f       = (const float*)d_in[1];
    const float* dt      = (const float*)d_in[2];
    const int*   src_idx = (const int*)d_in[3];
    const int*   dst_idx = (const int*)d_in[4];
    const float* w_t     = (const float*)d_in[5];
    const float* b_t     = (const float*)d_in[6];
    const float* Wq      = (const float*)d_in[7];
    const float* bq      = (const float*)d_in[8];
    const float* Wk      = (const float*)d_in[9];
    // d_in[10] = bk
    const float* bk      = (const float*)d_in[10];
    const float* Wv      = (const float*)d_in[11];
    const float* bv      = (const float*)d_in[12];
    const float* Wout    = (const float*)d_in[13];
    const float* bout    = (const float*)d_in[14];
    const float* ln_w    = (const float*)d_in[15];
    const float* ln_b    = (const float*)d_in[16];
    float* out = (float*)d_out;

    int E = in_sizes[2];
    int nch = (NDST + 511) / 512;

    k_zero<<<(NDST + 255) / 256, 256>>>();
    k_prep<<<1, 128>>>(Wq, bq, b_t);
    k_hist<<<(E + 255) / 256, 256>>>(dst_idx, E);
    k_scan1<<<nch, 512>>>();
    k_scan2<<<1, 32>>>(nch);
    k_scan3<<<(NDST + 255) / 256, 256>>>();
    k_scatter<<<(E + 255) / 256, 256>>>(dst_idx, E);
    k_qu<<<(NDST + 31) / 32, 256>>>(h, Wq, Wk, bk);
    k_attn<<<(NDST + 7) / 8, 256>>>(h, f, dt, src_idx, w_t, b_t);
    k_agg<<<(NDST + 15) / 16, 256>>>(Wv, bv);
    k_out<<<(NDST + 15) / 16, 256>>>(h, Wout, bout, ln_w, ln_b, out);
}

// round 2
// speedup vs baseline: 4.8723x; 4.8723x over previous
#include <cuda_runtime.h>
#include <math.h>

#define NDST 25000
#define DIM 128
#define DT_DIM 100
#define DQ 228          // 128 + 100
#define DK 356          // 128 + 128 + 100
#define UW 712          // 2 heads * 356
#define EMAX 400000
#define LEAKYC 0.2f
#define EPSC 1e-5f

#define INV2PI 0.15915494309189535f
#define PI2_A  6.2831854820251465f      // fp32 nearest to 2pi (slightly > 2pi)
#define PI2_B  1.7484556000744415e-07f  // PI2_A - 2pi

// ---------------- device scratch (no allocations allowed) ----------------
__device__ float d_cq[DIM];
__device__ float d_QB[NDST * 2];
__device__ int   d_counts[NDST];
__device__ int   d_starts[NDST];
__device__ int   d_cursor[NDST];
__device__ int   d_incl[NDST];
__device__ int   d_csum[64];
__device__ int   d_coff[64];
__device__ int   d_order[EMAX];
__device__ __align__(16) float d_U[(size_t)NDST * UW];     // 71 MB
__device__ __align__(16) float d_T[(size_t)NDST * UW];     // 71 MB
__device__ __align__(16) float d_QN[(size_t)NDST * DIM];   // 12.8 MB
__device__ __align__(16) float d_AGG[(size_t)NDST * DIM];  // 12.8 MB
__device__ __align__(16) float d_WqT[128 * 128];
__device__ __align__(16) float d_WvT[DK * 128];
__device__ __align__(16) float d_WoT[256 * 128];

// ---------------- tiny setup kernels ----------------
__global__ void k_zero() {
    int i = blockIdx.x * blockDim.x + threadIdx.x;
    if (i < NDST) { d_counts[i] = 0; d_cursor[i] = 0; }
}

__global__ void k_prep(const float* __restrict__ Wq, const float* __restrict__ bq,
                       const float* __restrict__ b_t) {
    int j = threadIdx.x;           // 128 threads
    float s = bq[j];
    for (int t = 0; t < DT_DIM; t++)
        s = fmaf(Wq[j * DQ + DIM + t], cosf(b_t[t]), s);
    d_cq[j] = s;
}

// transpose: out[c*R + r] = in[r*Cfull + c], c < Csub
__global__ void k_trs(const float* __restrict__ in, float* __restrict__ out,
                      int R, int Cfull, int Csub) {
    int idx = blockIdx.x * blockDim.x + threadIdx.x;
    int tot = R * Csub;
    if (idx < tot) {
        int c = idx / R, r = idx % R;
        out[idx] = in[r * Cfull + c];
    }
}

// ---------------- counting sort of edges by dst ----------------
__global__ void k_hist(const int* __restrict__ dst, int E) {
    int e = blockIdx.x * blockDim.x + threadIdx.x;
    if (e < E) atomicAdd(&d_counts[dst[e]], 1);
}

__global__ void k_scan1() {
    __shared__ int sm[512];
    int b = blockIdx.x, t = threadIdx.x;
    int i = b * 512 + t;
    sm[t] = (i < NDST) ? d_counts[i] : 0;
    __syncthreads();
    for (int off = 1; off < 512; off <<= 1) {
        int x = (t >= off) ? sm[t - off] : 0;
        __syncthreads();
        sm[t] += x;
        __syncthreads();
    }
    if (i < NDST) d_incl[i] = sm[t];
    if (t == 511) d_csum[b] = sm[t];
}

__global__ void k_scan2(int nch) {
    if (threadIdx.x == 0) {
        int run = 0;
        for (int b = 0; b < nch; b++) { d_coff[b] = run; run += d_csum[b]; }
    }
}

__global__ void k_scan3() {
    int i = blockIdx.x * blockDim.x + threadIdx.x;
    if (i < NDST) d_starts[i] = d_incl[i] - d_counts[i] + d_coff[i >> 9];
}

__global__ void k_scatter(const int* __restrict__ dst, int E) {
    int e = blockIdx.x * blockDim.x + threadIdx.x;
    if (e < E) {
        int d = dst[e];
        int pos = d_starts[d] + atomicAdd(&d_cursor[d], 1);
        d_order[pos] = e;
    }
}

// ---------------- qn = h[:NDST] @ WqT + cq   (tiled GEMM 64n x 128j) ----------------
__global__ void k_q(const float* __restrict__ h) {
    __shared__ float As[64 * 32];   // [n][ii]
    __shared__ float Bs[32 * 128];  // [ii][j]
    int nb = blockIdx.x * 64;
    int t = threadIdx.x;
    int j0 = (t & 31) * 4, n0 = (t >> 5) * 8;
    float acc[8][4];
#pragma unroll
    for (int r = 0; r < 8; r++)
#pragma unroll
        for (int q = 0; q < 4; q++) acc[r][q] = 0.f;

    for (int ch = 0; ch < 4; ch++) {
        int i0 = ch * 32;
        // stage A: coalesced in ii
        {
            int ii = t & 31, n = t >> 5;
#pragma unroll
            for (int p = 0; p < 8; p++) {
                int nn = n + p * 8;
                As[nn * 32 + ii] = (nb + nn < NDST) ? h[(size_t)(nb + nn) * DIM + i0 + ii] : 0.f;
            }
        }
        // stage B from WqT (K-major): coalesced in j
        {
            int j = t & 127, ii = t >> 7;
#pragma unroll
            for (int p = 0; p < 16; p++) {
                int i2 = ii + p * 2;
                Bs[i2 * 128 + j] = d_WqT[(size_t)(i0 + i2) * 128 + j];
            }
        }
        __syncthreads();
#pragma unroll
        for (int ii = 0; ii < 32; ii++) {
            float4 b4 = *(const float4*)&Bs[ii * 128 + j0];
#pragma unroll
            for (int r = 0; r < 8; r++) {
                float a = As[(n0 + r) * 32 + ii];
                acc[r][0] = fmaf(a, b4.x, acc[r][0]);
                acc[r][1] = fmaf(a, b4.y, acc[r][1]);
                acc[r][2] = fmaf(a, b4.z, acc[r][2]);
                acc[r][3] = fmaf(a, b4.w, acc[r][3]);
            }
        }
        __syncthreads();
    }
    float c0 = d_cq[j0], c1 = d_cq[j0 + 1], c2 = d_cq[j0 + 2], c3 = d_cq[j0 + 3];
#pragma unroll
    for (int r = 0; r < 8; r++) {
        int n = nb + n0 + r;
        if (n < NDST) {
            float* o = d_QN + (size_t)n * DIM + j0;
            o[0] = acc[r][0] + c0; o[1] = acc[r][1] + c1;
            o[2] = acc[r][2] + c2; o[3] = acc[r][3] + c3;
        }
    }
}

// ---------------- QB[n,h] = qn[n, h*64:]. bk[h*64:] ----------------
__global__ void k_qb(const float* __restrict__ bk) {
    int w = threadIdx.x >> 5, l = threadIdx.x & 31;
    int n = blockIdx.x * 8 + w;
    if (n >= NDST) return;
    const float* qp = d_QN + (size_t)n * DIM;
    float s0 = qp[l] * bk[l] + qp[32 + l] * bk[32 + l];
    float s1 = qp[64 + l] * bk[64 + l] + qp[96 + l] * bk[96 + l];
#pragma unroll
    for (int o = 16; o > 0; o >>= 1) {
        s0 += __shfl_xor_sync(0xffffffffu, s0, o);
        s1 += __shfl_xor_sync(0xffffffffu, s1, o);
    }
    if (l == 0) { d_QB[n * 2] = s0; d_QB[n * 2 + 1] = s1; }
}

// ---------------- U[n, h*356+c] = sum_jj qn[n,h*64+jj] * Wk[h*64+jj, c] ----------------
__global__ void k_u(const float* __restrict__ Wk) {
    __shared__ float As[64 * 32];   // [n][jj]
    __shared__ float Bs[32 * 128];  // [jj][c]
    int nb = blockIdx.x * 64;
    int c0 = blockIdx.y * 128;
    int hh = blockIdx.z;
    int t = threadIdx.x;
    int cl0 = (t & 31) * 4, n0 = (t >> 5) * 8;
    float acc[8][4];
#pragma unroll
    for (int r = 0; r < 8; r++)
#pragma unroll
        for (int q = 0; q < 4; q++) acc[r][q] = 0.f;

    for (int ch = 0; ch < 2; ch++) {
        int jj0 = ch * 32;
        {
            int jj = t & 31, n = t >> 5;
#pragma unroll
            for (int p = 0; p < 8; p++) {
                int nn = n + p * 8;
                As[nn * 32 + jj] = (nb + nn < NDST)
                    ? d_QN[(size_t)(nb + nn) * DIM + hh * 64 + jj0 + jj] : 0.f;
            }
        }
        {
            int c = t & 127, jj = t >> 7;
#pragma unroll
            for (int p = 0; p < 16; p++) {
                int j2 = jj + p * 2;
                Bs[j2 * 128 + c] = (c0 + c < DK)
                    ? Wk[(size_t)(hh * 64 + jj0 + j2) * DK + c0 + c] : 0.f;
            }
        }
        __syncthreads();
#pragma unroll
        for (int jj = 0; jj < 32; jj++) {
            float4 b4 = *(const float4*)&Bs[jj * 128 + cl0];
#pragma unroll
            for (int r = 0; r < 8; r++) {
                float a = As[(n0 + r) * 32 + jj];
                acc[r][0] = fmaf(a, b4.x, acc[r][0]);
                acc[r][1] = fmaf(a, b4.y, acc[r][1]);
                acc[r][2] = fmaf(a, b4.z, acc[r][2]);
                acc[r][3] = fmaf(a, b4.w, acc[r][3]);
            }
        }
        __syncthreads();
    }
#pragma unroll
    for (int r = 0; r < 8; r++) {
        int n = nb + n0 + r;
        if (n < NDST) {
            float* o = d_U + (size_t)n * UW + hh * DK;
#pragma unroll
            for (int q = 0; q < 4; q++) {
                int c = c0 + cl0 + q;
                if (c < DK) o[c] = acc[r][q];
            }
        }
    }
}

// ---------------- warp-per-dst fused attention (online softmax, float4) ----------------
__global__ void k_attn(const float* __restrict__ h, const float* __restrict__ f,
                       const float* __restrict__ dt, const int* __restrict__ src_idx,
                       const float* __restrict__ w_t, const float* __restrict__ b_t) {
    int wid = blockIdx.x * 8 + (threadIdx.x >> 5);
    int l = threadIdx.x & 31;
    if (wid >= NDST) return;
    int n = wid;
    int start = d_starts[n];
    int cnt = d_counts[n];

    const float4 z4 = make_float4(0.f, 0.f, 0.f, 0.f);
    const float4* up = (const float4*)(d_U + (size_t)n * UW);
    float4 Ua0 = up[l], Ua1 = up[32 + l], Ua2 = (l < 25) ? up[64 + l] : z4;
    float4 Ub0 = up[89 + l], Ub1 = up[121 + l], Ub2 = (l < 25) ? up[153 + l] : z4;
    float4 Ta0 = z4, Ta1 = z4, Ta2 = z4, Tb0 = z4, Tb1 = z4, Tb2 = z4;

    float qb0 = d_QB[n * 2], qb1 = d_QB[n * 2 + 1];
    float4 tw = (l < 25) ? ((const float4*)w_t)[l] : z4;
    float4 tb = (l < 25) ? ((const float4*)b_t)[l] : z4;

    float ninf = __int_as_float(0xff800000);
    float m0 = ninf, m1 = ninf, s0 = 0.f, s1 = 0.f;

    int e_cur = 0, src_cur = 0;
    float dt_cur = 0.f;
    if (cnt > 0) {
        e_cur = d_order[start];
        src_cur = src_idx[e_cur];
        dt_cur = dt[e_cur];
    }

    for (int i = 0; i < cnt; i++) {
        // prefetch next edge's scalars
        int e_nxt = 0, src_nxt = 0;
        float dt_nxt = 0.f;
        if (i + 1 < cnt) {
            e_nxt = d_order[start + i + 1];
            src_nxt = src_idx[e_nxt];
            dt_nxt = dt[e_nxt];
        }

        const float4* hp = (const float4*)(h + (size_t)src_cur * DIM);
        const float4* fp = (const float4*)(f + (size_t)e_cur * DIM);
        float4 kvh = hp[l];
        float4 kvf = __ldcs(&fp[l]);

        float4 kvt = z4;
        if (l < 25) {
            float y, kk, rr;
            y = __fadd_rn(__fmul_rn(dt_cur, tw.x), tb.x);
            kk = rintf(y * INV2PI); rr = fmaf(-kk, PI2_A, y); rr = fmaf(kk, PI2_B, rr);
            kvt.x = __cosf(rr);
            y = __fadd_rn(__fmul_rn(dt_cur, tw.y), tb.y);
            kk = rintf(y * INV2PI); rr = fmaf(-kk, PI2_A, y); rr = fmaf(kk, PI2_B, rr);
            kvt.y = __cosf(rr);
            y = __fadd_rn(__fmul_rn(dt_cur, tw.z), tb.z);
            kk = rintf(y * INV2PI); rr = fmaf(-kk, PI2_A, y); rr = fmaf(kk, PI2_B, rr);
            kvt.z = __cosf(rr);
            y = __fadd_rn(__fmul_rn(dt_cur, tw.w), tb.w);
            kk = rintf(y * INV2PI); rr = fmaf(-kk, PI2_A, y); rr = fmaf(kk, PI2_B, rr);
            kvt.w = __cosf(rr);
        }

        float sc0 = Ua0.x * kvh.x + Ua0.y * kvh.y + Ua0.z * kvh.z + Ua0.w * kvh.w;
        sc0 = fmaf(Ua1.x, kvf.x, sc0); sc0 = fmaf(Ua1.y, kvf.y, sc0);
        sc0 = fmaf(Ua1.z, kvf.z, sc0); sc0 = fmaf(Ua1.w, kvf.w, sc0);
        sc0 = fmaf(Ua2.x, kvt.x, sc0); sc0 = fmaf(Ua2.y, kvt.y, sc0);
        sc0 = fmaf(Ua2.z, kvt.z, sc0); sc0 = fmaf(Ua2.w, kvt.w, sc0);
        float sc1 = Ub0.x * kvh.x + Ub0.y * kvh.y + Ub0.z * kvh.z + Ub0.w * kvh.w;
        sc1 = fmaf(Ub1.x, kvf.x, sc1); sc1 = fmaf(Ub1.y, kvf.y, sc1);
        sc1 = fmaf(Ub1.z, kvf.z, sc1); sc1 = fmaf(Ub1.w, kvf.w, sc1);
        sc1 = fmaf(Ub2.x, kvt.x, sc1); sc1 = fmaf(Ub2.y, kvt.y, sc1);
        sc1 = fmaf(Ub2.z, kvt.z, sc1); sc1 = fmaf(Ub2.w, kvt.w, sc1);
#pragma unroll
        for (int o = 16; o > 0; o >>= 1) {
            sc0 += __shfl_xor_sync(0xffffffffu, sc0, o);
            sc1 += __shfl_xor_sync(0xffffffffu, sc1, o);
        }
        sc0 += qb0; sc1 += qb1;
        sc0 = sc0 >= 0.f ? sc0 : LEAKYC * sc0;
        sc1 = sc1 >= 0.f ? sc1 : LEAKYC * sc1;

        float nm0 = fmaxf(m0, sc0), nm1 = fmaxf(m1, sc1);
        float cr0 = __expf(m0 - nm0), cr1 = __expf(m1 - nm1);
        float e0 = __expf(sc0 - nm0), e1 = __expf(sc1 - nm1);
        s0 = s0 * cr0 + e0;
        s1 = s1 * cr1 + e1;
        Ta0.x = fmaf(Ta0.x, cr0, e0 * kvh.x); Ta0.y = fmaf(Ta0.y, cr0, e0 * kvh.y);
        Ta0.z = fmaf(Ta0.z, cr0, e0 * kvh.z); Ta0.w = fmaf(Ta0.w, cr0, e0 * kvh.w);
        Ta1.x = fmaf(Ta1.x, cr0, e0 * kvf.x); Ta1.y = fmaf(Ta1.y, cr0, e0 * kvf.y);
        Ta1.z = fmaf(Ta1.z, cr0, e0 * kvf.z); Ta1.w = fmaf(Ta1.w, cr0, e0 * kvf.w);
        Ta2.x = fmaf(Ta2.x, cr0, e0 * kvt.x); Ta2.y = fmaf(Ta2.y, cr0, e0 * kvt.y);
        Ta2.z = fmaf(Ta2.z, cr0, e0 * kvt.z); Ta2.w = fmaf(Ta2.w, cr0, e0 * kvt.w);
        Tb0.x = fmaf(Tb0.x, cr1, e1 * kvh.x); Tb0.y = fmaf(Tb0.y, cr1, e1 * kvh.y);
        Tb0.z = fmaf(Tb0.z, cr1, e1 * kvh.z); Tb0.w = fmaf(Tb0.w, cr1, e1 * kvh.w);
        Tb1.x = fmaf(Tb1.x, cr1, e1 * kvf.x); Tb1.y = fmaf(Tb1.y, cr1, e1 * kvf.y);
        Tb1.z = fmaf(Tb1.z, cr1, e1 * kvf.z); Tb1.w = fmaf(Tb1.w, cr1, e1 * kvf.w);
        Tb2.x = fmaf(Tb2.x, cr1, e1 * kvt.x); Tb2.y = fmaf(Tb2.y, cr1, e1 * kvt.y);
        Tb2.z = fmaf(Tb2.z, cr1, e1 * kvt.z); Tb2.w = fmaf(Tb2.w, cr1, e1 * kvt.w);
        m0 = nm0; m1 = nm1;

        e_cur = e_nxt; src_cur = src_nxt; dt_cur = dt_nxt;
    }

    float r0 = s0 > 0.f ? 1.f / s0 : 0.f;
    float r1 = s1 > 0.f ? 1.f / s1 : 0.f;
    float4* tp = (float4*)(d_T + (size_t)n * UW);
    tp[l] = make_float4(Ta0.x * r0, Ta0.y * r0, Ta0.z * r0, Ta0.w * r0);
    tp[32 + l] = make_float4(Ta1.x * r0, Ta1.y * r0, Ta1.z * r0, Ta1.w * r0);
    if (l < 25) tp[64 + l] = make_float4(Ta2.x * r0, Ta2.y * r0, Ta2.z * r0, Ta2.w * r0);
    tp[89 + l] = make_float4(Tb0.x * r1, Tb0.y * r1, Tb0.z * r1, Tb0.w * r1);
    tp[121 + l] = make_float4(Tb1.x * r1, Tb1.y * r1, Tb1.z * r1, Tb1.w * r1);
    if (l < 25) tp[153 + l] = make_float4(Tb2.x * r1, Tb2.y * r1, Tb2.z * r1, Tb2.w * r1);
}

// ---------------- agg[n, h*64+o] = sum_c T[n,h*356+c] * WvT[c, h*64+o] + bv ----------------
__global__ void k_agg(const float* __restrict__ bv) {
    __shared__ float As[64 * 32];   // [n][cc]
    __shared__ float Bs[32 * 64];   // [cc][o]
    int nb = blockIdx.x * 64;
    int hh = blockIdx.y;
    int t = threadIdx.x;
    int o0 = (t & 15) * 4, n0 = (t >> 4) * 4;
    float acc[4][4];
#pragma unroll
    for (int r = 0; r < 4; r++)
#pragma unroll
        for (int q = 0; q < 4; q++) acc[r][q] = 0.f;

    for (int ch = 0; ch < 12; ch++) {
        int c0 = ch * 32;
        {
            int cc = t & 31, nn = t >> 5;
#pragma unroll
            for (int p = 0; p < 8; p++) {
                int n = nn + p * 8;
                As[n * 32 + cc] = (nb + n < NDST && c0 + cc < DK)
                    ? d_T[(size_t)(nb + n) * UW + hh * DK + c0 + cc] : 0.f;
            }
        }
        {
            int o = t & 63, cc = t >> 6;
#pragma unroll
            for (int p = 0; p < 8; p++) {
                int c2 = cc + p * 4;
                Bs[c2 * 64 + o] = (c0 + c2 < DK)
                    ? d_WvT[(size_t)(c0 + c2) * 128 + hh * 64 + o] : 0.f;
            }
        }
        __syncthreads();
#pragma unroll
        for (int cc = 0; cc < 32; cc++) {
            float4 b4 = *(const float4*)&Bs[cc * 64 + o0];
#pragma unroll
            for (int r = 0; r < 4; r++) {
                float a = As[(n0 + r) * 32 + cc];
                acc[r][0] = fmaf(a, b4.x, acc[r][0]);
                acc[r][1] = fmaf(a, b4.y, acc[r][1]);
                acc[r][2] = fmaf(a, b4.z, acc[r][2]);
                acc[r][3] = fmaf(a, b4.w, acc[r][3]);
            }
        }
        __syncthreads();
    }
#pragma unroll
    for (int r = 0; r < 4; r++) {
        int n = nb + n0 + r;
        if (n < NDST) {
            bool has = d_counts[n] > 0;
            float* o = d_AGG + (size_t)n * DIM + hh * 64 + o0;
#pragma unroll
            for (int q = 0; q < 4; q++)
                o[q] = acc[r][q] + (has ? bv[hh * 64 + o0 + q] : 0.f);
        }
    }
}

// ---------------- rst = relu([agg,h] @ WoutT + bout) -> LayerNorm ----------------
__global__ void k_out(const float* __restrict__ h, const float* __restrict__ bout,
                      const float* __restrict__ ln_w, const float* __restrict__ ln_b,
                      float* __restrict__ out) {
    __shared__ float smem_buf[64 * 128];  // 32 KB, aliased: GEMM stage then rst
    float* As = smem_buf;                 // [64][32]
    float* Bs = smem_buf + 64 * 32;       // [32][128]
    int nb = blockIdx.x * 64;
    int t = threadIdx.x;
    int j0 = (t & 31) * 4, n0 = (t >> 5) * 8;
    float acc[8][4];
#pragma unroll
    for (int r = 0; r < 8; r++)
#pragma unroll
        for (int q = 0; q < 4; q++) acc[r][q] = 0.f;

    for (int ch = 0; ch < 8; ch++) {
        int p0 = ch * 32;
        {
            int pp = t & 31, nn = t >> 5;
            const float* srcp = (p0 < 128) ? (d_AGG + p0) : (h + (p0 - 128));
#pragma unroll
            for (int p = 0; p < 8; p++) {
                int n = nn + p * 8;
                As[n * 32 + pp] = (nb + n < NDST)
                    ? srcp[(size_t)(nb + n) * DIM + pp] : 0.f;
            }
        }
        {
            int j = t & 127, pp = t >> 7;
#pragma unroll
            for (int p = 0; p < 16; p++) {
                int p2 = pp + p * 2;
                Bs[p2 * 128 + j] = d_WoT[(size_t)(p0 + p2) * 128 + j];
            }
        }
        __syncthreads();
#pragma unroll
        for (int pp = 0; pp < 32; pp++) {
            float4 b4 = *(const float4*)&Bs[pp * 128 + j0];
#pragma unroll
            for (int r = 0; r < 8; r++) {
                float a = As[(n0 + r) * 32 + pp];
                acc[r][0] = fmaf(a, b4.x, acc[r][0]);
                acc[r][1] = fmaf(a, b4.y, acc[r][1]);
                acc[r][2] = fmaf(a, b4.z, acc[r][2]);
                acc[r][3] = fmaf(a, b4.w, acc[r][3]);
            }
        }
        __syncthreads();
    }
    // relu -> Rs (reuse smem)
    float b0 = bout[j0], b1 = bout[j0 + 1], b2 = bout[j0 + 2], b3 = bout[j0 + 3];
    float* Rs = smem_buf;
#pragma unroll
    for (int r = 0; r < 8; r++) {
        float4 v;
        v.x = fmaxf(acc[r][0] + b0, 0.f);
        v.y = fmaxf(acc[r][1] + b1, 0.f);
        v.z = fmaxf(acc[r][2] + b2, 0.f);
        v.w = fmaxf(acc[r][3] + b3, 0.f);
        *(float4*)&Rs[(n0 + r) * 128 + j0] = v;
    }
    __syncthreads();

    // LayerNorm: 8 warps x 8 rows
    int w = t >> 5, l = t & 31;
    float lw0 = ln_w[l], lw1 = ln_w[l + 32], lw2 = ln_w[l + 64], lw3 = ln_w[l + 96];
    float lb0 = ln_b[l], lb1 = ln_b[l + 32], lb2 = ln_b[l + 64], lb3 = ln_b[l + 96];
    for (int rr = 0; rr < 8; rr++) {
        int nl = w * 8 + rr;
        float v0 = Rs[nl * 128 + l], v1 = Rs[nl * 128 + l + 32];
        float v2 = Rs[nl * 128 + l + 64], v3 = Rs[nl * 128 + l + 96];
        float s = v0 + v1 + v2 + v3;
#pragma unroll
        for (int off = 16; off > 0; off >>= 1) s += __shfl_xor_sync(0xffffffffu, s, off);
        float mu = s * (1.f / 128.f);
        float d0 = v0 - mu, d1 = v1 - mu, d2 = v2 - mu, d3 = v3 - mu;
        float vs = d0 * d0 + d1 * d1 + d2 * d2 + d3 * d3;
#pragma unroll
        for (int off = 16; off > 0; off >>= 1) vs += __shfl_xor_sync(0xffffffffu, vs, off);
        float rstd = rsqrtf(vs * (1.f / 128.f) + EPSC);
        int ng = nb + nl;
        if (ng < NDST) {
            float* op = out + (size_t)ng * DIM;
            op[l] = d0 * rstd * lw0 + lb0;
            op[l + 32] = d1 * rstd * lw1 + lb1;
            op[l + 64] = d2 * rstd * lw2 + lb2;
            op[l + 96] = d3 * rstd * lw3 + lb3;
        }
    }
}

// ---------------- launch ----------------
extern "C" void kernel_launch(void* const* d_in, const int* in_sizes, int n_in,
                              void* d_out, int out_size) {
    const float* h       = (const float*)d_in[0];
    const float* f       = (const float*)d_in[1];
    const float* dt      = (const float*)d_in[2];
    const int*   src_idx = (const int*)d_in[3];
    const int*   dst_idx = (const int*)d_in[4];
    const float* w_t     = (const float*)d_in[5];
    const float* b_t     = (const float*)d_in[6];
    const float* Wq      = (const float*)d_in[7];
    const float* bq      = (const float*)d_in[8];
    const float* Wk      = (const float*)d_in[9];
    const float* bk      = (const float*)d_in[10];
    const float* Wv      = (const float*)d_in[11];
    const float* bv      = (const float*)d_in[12];
    const float* Wout    = (const float*)d_in[13];
    const float* bout    = (const float*)d_in[14];
    const float* ln_w    = (const float*)d_in[15];
    const float* ln_b    = (const float*)d_in[16];
    float* out = (float*)d_out;

    int E = in_sizes[2];
    int nch = (NDST + 511) / 512;
    int nb64 = (NDST + 63) / 64;

    float *p_WqT, *p_WvT, *p_WoT;
    cudaGetSymbolAddress((void**)&p_WqT, d_WqT);
    cudaGetSymbolAddress((void**)&p_WvT, d_WvT);
    cudaGetSymbolAddress((void**)&p_WoT, d_WoT);

    k_zero<<<(NDST + 255) / 256, 256>>>();
    k_prep<<<1, 128>>>(Wq, bq, b_t);
    k_trs<<<(128 * 128 + 255) / 256, 256>>>(Wq, p_WqT, 128, DQ, 128);
    k_trs<<<(DK * 128 + 255) / 256, 256>>>(Wv, p_WvT, 128, DK, DK);
    k_trs<<<(256 * 128 + 255) / 256, 256>>>(Wout, p_WoT, 128, 256, 256);
    k_hist<<<(E + 255) / 256, 256>>>(dst_idx, E);
    k_scan1<<<nch, 512>>>();
    k_scan2<<<1, 32>>>(nch);
    k_scan3<<<(NDST + 255) / 256, 256>>>();
    k_scatter<<<(E + 255) / 256, 256>>>(dst_idx, E);
    k_q<<<nb64, 256>>>(h);
    k_qb<<<(NDST + 7) / 8, 256>>>(bk);
    k_u<<<dim3(nb64, 3, 2), 256>>>(Wk);
    k_attn<<<(NDST + 7) / 8, 256>>>(h, f, dt, src_idx, w_t, b_t);
    k_agg<<<dim3(nb64, 2), 256>>>(bv);
    k_out<<<nb64, 256>>>(h, bout, ln_w, ln_b, out);
}